// round 15
// baseline (speedup 1.0000x reference)
#include <cuda_runtime.h>
#include <cuda_fp16.h>
#include <math.h>

// ---------------------------------------------------------------------------
// BasicTransformerBlock on GB300 — fp16 mma.sync (m16n8k16) everywhere.
// R14 + 128-row q-tiles in flash attention (halved K/V L2 traffic) +
// fused wk1/wv1 GEMM (strided kv1 buffer).
// x:[8,1024,512], enc:[8,77,768]. Heads=8, dim_head=64.
// ---------------------------------------------------------------------------

#define DIM 512
#define ROWS 8192
#define CROSS_ROWS 616
#define CROSS_DIM 768
#define FF_INNER 2048
#define FF2 4096

#define OFF_WQ1 0u
#define OFF_WK1 262144u   // contiguous with WV1 for fused KV1 GEMM
#define OFF_WV1 524288u
#define OFF_WO1 786432u
#define OFF_WQ2 1048576u
#define OFF_WO2 1310720u
#define OFF_WK2 1572864u
#define OFF_WV2 1966080u  // contiguous with WK2 for fused KV2 GEMM
#define OFF_WG  2359296u
#define OFF_WF  4456448u
#define WT_TOTAL 5505024u

__device__ __half g_h[ROWS * DIM];
__device__ __half g_q[ROWS * DIM];
__device__ __half g_kv1[ROWS * 1024];
__device__ __half g_a[ROWS * DIM];
__device__ __half g_act[ROWS * FF_INNER];
__device__ __half g_kv[CROSS_ROWS * 1024];
__device__ float  g_x1[ROWS * DIM];
__device__ float  g_x2[ROWS * DIM];
__device__ __half g_wth[WT_TOTAL];
__device__ __half g_ench[CROSS_ROWS * CROSS_DIM];

// ---------------------------------------------------------------------------
// helpers
// ---------------------------------------------------------------------------
__device__ __forceinline__ void mma16(float* acc, const unsigned* a, const unsigned* b) {
    asm volatile(
        "mma.sync.aligned.m16n8k16.row.col.f32.f16.f16.f32 "
        "{%0,%1,%2,%3}, {%4,%5,%6,%7}, {%8,%9}, {%0,%1,%2,%3};"
        : "+f"(acc[0]), "+f"(acc[1]), "+f"(acc[2]), "+f"(acc[3])
        : "r"(a[0]), "r"(a[1]), "r"(a[2]), "r"(a[3]), "r"(b[0]), "r"(b[1]));
}
__device__ __forceinline__ void ldsm4(unsigned& r0, unsigned& r1, unsigned& r2, unsigned& r3,
                                      unsigned addr) {
    asm volatile("ldmatrix.sync.aligned.m8n8.x4.shared.b16 {%0,%1,%2,%3}, [%4];"
                 : "=r"(r0), "=r"(r1), "=r"(r2), "=r"(r3) : "r"(addr));
}
__device__ __forceinline__ void ldsm4t(unsigned& r0, unsigned& r1, unsigned& r2, unsigned& r3,
                                       unsigned addr) {
    asm volatile("ldmatrix.sync.aligned.m8n8.x4.trans.shared.b16 {%0,%1,%2,%3}, [%4];"
                 : "=r"(r0), "=r"(r1), "=r"(r2), "=r"(r3) : "r"(addr));
}
__device__ __forceinline__ void cpa16(unsigned dst, const void* src, bool pred) {
    int sz = pred ? 16 : 0;
    asm volatile("cp.async.cg.shared.global [%0], [%1], 16, %2;"
                 :: "r"(dst), "l"(src), "r"(sz) : "memory");
}
__device__ __forceinline__ void cpa_commit() {
    asm volatile("cp.async.commit_group;" ::: "memory");
}
template <int N>
__device__ __forceinline__ void cpa_wait() {
    asm volatile("cp.async.wait_group %0;" :: "n"(N) : "memory");
}
__device__ __forceinline__ unsigned packh2(float lo, float hi) {
    __half2 h = __floats2half2_rn(lo, hi);
    return *reinterpret_cast<unsigned*>(&h);
}
__device__ __forceinline__ float gelu_f(float x) {
    return 0.5f * x * (1.f + erff(x * 0.70710678118654752f));
}

// ---------------------------------------------------------------------------
// fused prologue: transpose+convert all 10 weights [K,N]->[N,K] half
// (weight 8 = wg gets GEGLU column interleave), plus enc f2h tail blocks.
// ---------------------------------------------------------------------------
struct TP {
    const float* src[10];
    unsigned off[10];
    int K[10], N[10], cum[10];
    const float* enc;
    int encN;
};

__global__ __launch_bounds__(256) void transp_all(TP p, __half* __restrict__ wt,
                                                  __half* __restrict__ ench)
{
    __shared__ float t[32][33];
    int bid = blockIdx.x;
    if (bid >= p.cum[9]) {
        int base = (bid - p.cum[9]) * 2048 + threadIdx.y * 32 * 8 + threadIdx.x;
#pragma unroll
        for (int i = 0; i < 8; i++) {
            int idx = base + i * 32;
            if (idx < p.encN) ench[idx] = __float2half(p.enc[idx]);
        }
        return;
    }
    int w = 0;
#pragma unroll
    for (int i = 0; i < 10; i++) if (bid >= p.cum[i]) w = i + 1;
    int tbase = w ? p.cum[w - 1] : 0;
    int tile = bid - tbase;
    int K = p.K[w], N = p.N[w];
    int tilesX = N >> 5;
    int bx = (tile % tilesX) * 32;
    int by = (tile / tilesX) * 32;
    const float* src = p.src[w];
    __half* dst = wt + p.off[w];

    int tx = threadIdx.x, ty = threadIdx.y;
#pragma unroll
    for (int i = 0; i < 4; i++)
        t[ty + 8 * i][tx] = src[(size_t)(by + ty + 8 * i) * N + bx + tx];
    __syncthreads();
#pragma unroll
    for (int i = 0; i < 4; i++) {
        int c = bx + ty + 8 * i;
        int nr = c;
        if (w == 8) {
            if (c < 2048) nr = ((c >> 4) << 5) + (c & 15);
            else { int cc = c - 2048; nr = ((cc >> 4) << 5) + 16 + (cc & 15); }
        }
        dst[(size_t)nr * K + by + tx] = __float2half(t[tx][ty + 8 * i]);
    }
}

// ---------------------------------------------------------------------------
// fp16 tensor-core GEMM: C[M,N] = A[M,K] @ BT[N,K]^T  (+bias)(+res)
// 128x128x64 tile, 256 thr, 3-stage cp.async, one barrier/tile (frozen).
// GEGLU variant fuses act = (u+bu)*gelu(g+bg) via interleaved wg.
// ---------------------------------------------------------------------------
#define HA_STG 16384
#define HB_OFF 49152
#define HB_STG 16384
#define GH_SMEM 98304

template <bool BIAS, bool RES, bool OUTH, bool GEGLU>
__global__ __launch_bounds__(256) void gemm_h(
    const __half* __restrict__ A, const __half* __restrict__ BT,
    const float* __restrict__ bias, const float* __restrict__ res,
    void* __restrict__ Cout, int M, int N, int K)
{
    extern __shared__ char smem[];
    unsigned sb = (unsigned)__cvta_generic_to_shared(smem);

    int tid = threadIdx.x;
    int lane = tid & 31, warp = tid >> 5;
    int wm = warp >> 2, wn = warp & 3;
    int m0 = blockIdx.y * 128, n0 = blockIdx.x * 128;

    int srow = tid >> 1, sch = (tid & 1) * 4;
    bool aval = (m0 + srow) < M;
    const __half* ag = A + (size_t)(aval ? m0 + srow : 0) * K + sch * 8;
    const __half* bg = BT + (size_t)(n0 + srow) * K + sch * 8;
    unsigned ssw[4];
#pragma unroll
    for (int c = 0; c < 4; c++)
        ssw[c] = srow * 128 + (((sch + c) ^ (srow & 7)) << 4);

    auto stage = [&](int t, int buf) {
        unsigned ab = sb + buf * HA_STG;
        unsigned bb = sb + HB_OFF + buf * HB_STG;
        const __half* a = ag + t * 64;
        const __half* b = bg + t * 64;
#pragma unroll
        for (int c = 0; c < 4; c++) cpa16(ab + ssw[c], a + c * 8, aval);
#pragma unroll
        for (int c = 0; c < 4; c++) cpa16(bb + ssw[c], b + c * 8, true);
        cpa_commit();
    };

    int mat = lane >> 3, lr = lane & 7;
    int rA = wm * 64 + (mat & 1) * 8 + lr;
    int rB = wn * 32 + (mat & 1) * 8 + lr;
    int cOff = mat >> 1;

    float acc[4][4][4] = {};
    int nk = K >> 6;

    stage(0, 0);
    stage(1, 1);

    for (int t = 0; t < nk; t++) {
        int buf = t % 3;
        cpa_wait<1>();
        __syncthreads();
        if (t + 2 < nk) stage(t + 2, (t + 2) % 3);
        else cpa_commit();
        unsigned abase = sb + buf * HA_STG;
        unsigned bbase = sb + HB_OFF + buf * HB_STG;
#pragma unroll
        for (int ks = 0; ks < 4; ks++) {
            int cc = ks * 2 + cOff;
            unsigned bf[4][2];
#pragma unroll
            for (int p = 0; p < 2; p++) {
                int r = rB + p * 16;
                unsigned q0, q1, q2, q3;
                ldsm4(q0, q1, q2, q3, bbase + r * 128 + ((cc ^ (r & 7)) << 4));
                bf[2 * p][0] = q0; bf[2 * p][1] = q2;
                bf[2 * p + 1][0] = q1; bf[2 * p + 1][1] = q3;
            }
#pragma unroll
            for (int i = 0; i < 4; i++) {
                int r = rA + i * 16;
                unsigned af[4];
                ldsm4(af[0], af[1], af[2], af[3],
                      abase + r * 128 + ((cc ^ (r & 7)) << 4));
#pragma unroll
                for (int j = 0; j < 4; j++)
                    mma16(acc[i][j], af, bf[j]);
            }
        }
    }

    __syncthreads();

    if (GEGLU) {
        int t32 = (n0 + wn * 32) >> 5;
        __half* actp = (__half*)Cout;
#pragma unroll
        for (int i = 0; i < 4; i++) {
            int mbase = m0 + wm * 64 + i * 16 + (lane >> 2);
#pragma unroll
            for (int j = 0; j < 2; j++) {
                int off = j * 8 + (lane & 3) * 2;
                int col = t32 * 16 + off;
                float2 bu = *(const float2*)&bias[t32 * 16 + off];
                float2 bgv = *(const float2*)&bias[2048 + t32 * 16 + off];
                int m1 = mbase, m2 = mbase + 8;
                if (m1 < M) {
                    float ux = acc[i][j][0] + bu.x, uy = acc[i][j][1] + bu.y;
                    float gx = acc[i][j + 2][0] + bgv.x, gy = acc[i][j + 2][1] + bgv.y;
                    *(__half2*)&actp[(size_t)m1 * FF_INNER + col] =
                        __floats2half2_rn(ux * gelu_f(gx), uy * gelu_f(gy));
                }
                if (m2 < M) {
                    float ux = acc[i][j][2] + bu.x, uy = acc[i][j][3] + bu.y;
                    float gx = acc[i][j + 2][2] + bgv.x, gy = acc[i][j + 2][3] + bgv.y;
                    *(__half2*)&actp[(size_t)m2 * FF_INNER + col] =
                        __floats2half2_rn(ux * gelu_f(gx), uy * gelu_f(gy));
                }
            }
        }
        return;
    }

#pragma unroll
    for (int i = 0; i < 4; i++) {
        int mbase = m0 + wm * 64 + i * 16 + (lane >> 2);
#pragma unroll
        for (int j = 0; j < 4; j++) {
            int n = n0 + wn * 32 + j * 8 + (lane & 3) * 2;
            float bx = 0.f, by = 0.f;
            if (BIAS) { float2 bb = *(const float2*)&bias[n]; bx = bb.x; by = bb.y; }
            int m1 = mbase, m2 = mbase + 8;
            if (m1 < M) {
                float vx = acc[i][j][0] + bx, vy = acc[i][j][1] + by;
                if (RES) {
                    float2 rr = *(const float2*)&res[(size_t)m1 * N + n];
                    vx += rr.x; vy += rr.y;
                }
                if (OUTH)
                    *(__half2*)&((__half*)Cout)[(size_t)m1 * N + n] = __floats2half2_rn(vx, vy);
                else
                    *(float2*)&((float*)Cout)[(size_t)m1 * N + n] = make_float2(vx, vy);
            }
            if (m2 < M) {
                float vx = acc[i][j][2] + bx, vy = acc[i][j][3] + by;
                if (RES) {
                    float2 rr = *(const float2*)&res[(size_t)m2 * N + n];
                    vx += rr.x; vy += rr.y;
                }
                if (OUTH)
                    *(__half2*)&((__half*)Cout)[(size_t)m2 * N + n] = __floats2half2_rn(vx, vy);
                else
                    *(float2*)&((float*)Cout)[(size_t)m2 * N + n] = make_float2(vx, vy);
            }
        }
    }
}

// ---------------------------------------------------------------------------
// LayerNorm: one warp per row of 512, half output
// ---------------------------------------------------------------------------
__global__ __launch_bounds__(256) void ln_kernel(
    const float* __restrict__ x, const float* __restrict__ g,
    const float* __restrict__ b, __half* __restrict__ out, int rows)
{
    int row = blockIdx.x * 8 + (threadIdx.x >> 5);
    int lane = threadIdx.x & 31;
    if (row >= rows) return;
    const float4* xr = (const float4*)(x + (size_t)row * DIM);
    float4 v[4];
    float sum = 0.f, sq = 0.f;
#pragma unroll
    for (int i = 0; i < 4; i++) {
        v[i] = xr[lane + i * 32];
        sum += v[i].x + v[i].y + v[i].z + v[i].w;
        sq  += v[i].x*v[i].x + v[i].y*v[i].y + v[i].z*v[i].z + v[i].w*v[i].w;
    }
#pragma unroll
    for (int off = 16; off; off >>= 1) {
        sum += __shfl_xor_sync(0xffffffffu, sum, off);
        sq  += __shfl_xor_sync(0xffffffffu, sq,  off);
    }
    float mean = sum * (1.f / DIM);
    float var  = sq * (1.f / DIM) - mean * mean;
    float rstd = rsqrtf(var + 1e-5f);
    __half2* outr = (__half2*)(out + (size_t)row * DIM);
#pragma unroll
    for (int i = 0; i < 4; i++) {
        int c = (lane + i * 32) * 4;
        float4 gg = *(const float4*)&g[c];
        float4 bb = *(const float4*)&b[c];
        float ox = (v[i].x - mean) * rstd * gg.x + bb.x;
        float oy = (v[i].y - mean) * rstd * gg.y + bb.y;
        float oz = (v[i].z - mean) * rstd * gg.z + bb.z;
        float ow = (v[i].w - mean) * rstd * gg.w + bb.w;
        outr[(lane + i * 32) * 2]     = __floats2half2_rn(ox, oy);
        outr[(lane + i * 32) * 2 + 1] = __floats2half2_rn(oz, ow);
    }
}

// ---------------------------------------------------------------------------
// Flash attention, fp16 mma. 256 thr (8 warps), 128 q-rows/block, 64-key tiles.
// Each warp owns 16 q-rows (same per-warp shapes as before). K/V traffic per
// block amortized over 2x q-rows. ldkv = K/V row stride.
// smem (dynamic): Qs 16KB | Ks 2x8KB | Vs 2x8KB = 48KB.
// ---------------------------------------------------------------------------
#define FQ_BYTES 16384
#define FK_OFF 16384
#define FK_STG 8192
#define FV_OFF 32768
#define FA_SMEM 49152

__global__ __launch_bounds__(256) void fattn_h(
    const __half* __restrict__ Q, const __half* __restrict__ K,
    const __half* __restrict__ V, __half* __restrict__ O,
    int kRowsPerB, int Sk, int ldkv)
{
    extern __shared__ char fsm[];
    unsigned sQ = (unsigned)__cvta_generic_to_shared(fsm);
    unsigned sK = sQ + FK_OFF;
    unsigned sV = sQ + FV_OFF;

    int tid = threadIdx.x;
    int lane = tid & 31, warp = tid >> 5;
    int b = blockIdx.z, h = blockIdx.y;
    int q0 = blockIdx.x * 128;
    size_t qbase = ((size_t)b * 1024 + q0) * DIM + h * 64;
    size_t kbase = (size_t)b * kRowsPerB * ldkv + h * 64;

    // stage Q: 128 rows x 8 chunks = 1024 chunks over 256 threads
#pragma unroll
    for (int it = 0; it < 4; it++) {
        int c = tid + it * 256;
        int r = c >> 3, ch = c & 7;
        cpa16(sQ + r * 128 + ((ch ^ (r & 7)) << 4), Q + qbase + (size_t)r * DIM + ch * 8, true);
    }
    cpa_commit();

    int nkt = (Sk + 63) / 64;
    // prefetch K/V tiles 0,1 (64 rows x 8 chunks = 512 chunks over 256 thr)
#pragma unroll
    for (int t = 0; t < 2; t++) {
        if (t < nkt) {
#pragma unroll
            for (int it = 0; it < 2; it++) {
                int c = tid + it * 256;
                int r = c >> 3, ch = c & 7;
                int gr = t * 64 + r;
                bool ok = gr < Sk;
                unsigned sw = r * 128 + ((ch ^ (r & 7)) << 4);
                cpa16(sK + t * FK_STG + sw, K + kbase + (size_t)gr * ldkv + ch * 8, ok);
                cpa16(sV + t * FK_STG + sw, V + kbase + (size_t)gr * ldkv + ch * 8, ok);
            }
        }
        cpa_commit();
    }

    int mat = lane >> 3, lr = lane & 7;
    unsigned qa[4][4];
    {
        cpa_wait<2>();
        __syncthreads();
        int r = warp * 16 + (mat & 1) * 8 + lr;
#pragma unroll
        for (int ks = 0; ks < 4; ks++) {
            int cc = ks * 2 + (mat >> 1);
            ldsm4(qa[ks][0], qa[ks][1], qa[ks][2], qa[ks][3],
                  sQ + r * 128 + ((cc ^ (r & 7)) << 4));
        }
    }

    float m_[2] = {-1e30f, -1e30f};
    float l_[2] = {0.f, 0.f};
    float o[8][4] = {};

    for (int kt = 0; kt < nkt; kt++) {
        int cur = kt & 1;
        cpa_wait<1>();
        __syncthreads();

        unsigned kb = sK + cur * FK_STG;
        unsigned vb = sV + cur * FK_STG;

        float s[8][4] = {};
#pragma unroll
        for (int ks = 0; ks < 4; ks++) {
            int cc = ks * 2 + (mat >> 1);
            unsigned kf[8][2];
#pragma unroll
            for (int p = 0; p < 4; p++) {
                int r = p * 16 + (mat & 1) * 8 + lr;
                unsigned r0, r1, r2, r3;
                ldsm4(r0, r1, r2, r3, kb + r * 128 + ((cc ^ (r & 7)) << 4));
                kf[2 * p][0] = r0; kf[2 * p][1] = r2;
                kf[2 * p + 1][0] = r1; kf[2 * p + 1][1] = r3;
            }
#pragma unroll
            for (int j = 0; j < 8; j++)
                mma16(s[j], qa[ks], kf[j]);
        }
#pragma unroll
        for (int j = 0; j < 8; j++) {
            s[j][0] *= 0.125f; s[j][1] *= 0.125f; s[j][2] *= 0.125f; s[j][3] *= 0.125f;
        }
        if (kt * 64 + 64 > Sk) {
#pragma unroll
            for (int j = 0; j < 8; j++) {
                int cb = kt * 64 + j * 8 + (lane & 3) * 2;
                if (cb >= Sk)     { s[j][0] = -1e30f; s[j][2] = -1e30f; }
                if (cb + 1 >= Sk) { s[j][1] = -1e30f; s[j][3] = -1e30f; }
            }
        }
        float mx0 = -1e30f, mx1 = -1e30f;
#pragma unroll
        for (int j = 0; j < 8; j++) {
            mx0 = fmaxf(mx0, fmaxf(s[j][0], s[j][1]));
            mx1 = fmaxf(mx1, fmaxf(s[j][2], s[j][3]));
        }
#pragma unroll
        for (int off = 1; off < 4; off <<= 1) {
            mx0 = fmaxf(mx0, __shfl_xor_sync(0xffffffffu, mx0, off));
            mx1 = fmaxf(mx1, __shfl_xor_sync(0xffffffffu, mx1, off));
        }
        float mn0 = fmaxf(m_[0], mx0), mn1 = fmaxf(m_[1], mx1);
        float c0 = __expf(m_[0] - mn0), c1 = __expf(m_[1] - mn1);
        m_[0] = mn0; m_[1] = mn1;
        float sum0 = 0.f, sum1 = 0.f;
#pragma unroll
        for (int j = 0; j < 8; j++) {
            s[j][0] = __expf(s[j][0] - mn0); sum0 += s[j][0];
            s[j][1] = __expf(s[j][1] - mn0); sum0 += s[j][1];
            s[j][2] = __expf(s[j][2] - mn1); sum1 += s[j][2];
            s[j][3] = __expf(s[j][3] - mn1); sum1 += s[j][3];
        }
#pragma unroll
        for (int off = 1; off < 4; off <<= 1) {
            sum0 += __shfl_xor_sync(0xffffffffu, sum0, off);
            sum1 += __shfl_xor_sync(0xffffffffu, sum1, off);
        }
        l_[0] = l_[0] * c0 + sum0;
        l_[1] = l_[1] * c1 + sum1;
#pragma unroll
        for (int j = 0; j < 8; j++) {
            o[j][0] *= c0; o[j][1] *= c0;
            o[j][2] *= c1; o[j][3] *= c1;
        }

#pragma unroll
        for (int kk = 0; kk < 4; kk++) {
            unsigned pa[4];
            pa[0] = packh2(s[2 * kk][0],     s[2 * kk][1]);
            pa[1] = packh2(s[2 * kk][2],     s[2 * kk][3]);
            pa[2] = packh2(s[2 * kk + 1][0], s[2 * kk + 1][1]);
            pa[3] = packh2(s[2 * kk + 1][2], s[2 * kk + 1][3]);
            int r = kk * 16 + (mat & 1) * 8 + lr;
#pragma unroll
            for (int jp = 0; jp < 4; jp++) {
                int cc = jp * 2 + (mat >> 1);
                unsigned r0, r1, r2, r3;
                ldsm4t(r0, r1, r2, r3, vb + r * 128 + ((cc ^ (r & 7)) << 4));
                unsigned vf0[2] = {r0, r1};
                unsigned vf1[2] = {r2, r3};
                mma16(o[2 * jp], pa, vf0);
                mma16(o[2 * jp + 1], pa, vf1);
            }
        }
        __syncthreads();
        {
            int t = kt + 2;
            if (t < nkt) {
#pragma unroll
                for (int it = 0; it < 2; it++) {
                    int c = tid + it * 256;
                    int r = c >> 3, ch = c & 7;
                    int gr = t * 64 + r;
                    bool ok = gr < Sk;
                    unsigned sw = r * 128 + ((ch ^ (r & 7)) << 4);
                    cpa16(sK + cur * FK_STG + sw, K + kbase + (size_t)gr * ldkv + ch * 8, ok);
                    cpa16(sV + cur * FK_STG + sw, V + kbase + (size_t)gr * ldkv + ch * 8, ok);
                }
            }
            cpa_commit();
        }
    }

    float inv0 = 1.f / l_[0], inv1 = 1.f / l_[1];
    int r0 = warp * 16 + (lane >> 2);
#pragma unroll
    for (int j = 0; j < 8; j++) {
        int col = j * 8 + (lane & 3) * 2;
        *(__half2*)&O[qbase + (size_t)r0 * DIM + col] =
            __floats2half2_rn(o[j][0] * inv0, o[j][1] * inv0);
        *(__half2*)&O[qbase + (size_t)(r0 + 8) * DIM + col] =
            __floats2half2_rn(o[j][2] * inv1, o[j][3] * inv1);
    }
}

// ---------------------------------------------------------------------------
extern "C" void kernel_launch(void* const* d_in, const int* in_sizes, int n_in,
                              void* d_out, int out_size)
{
    const float* x     = (const float*)d_in[0];
    const float* enc   = (const float*)d_in[1];
    const float* ln1_g = (const float*)d_in[2];
    const float* ln1_b = (const float*)d_in[3];
    const float* wq1   = (const float*)d_in[4];
    const float* wk1   = (const float*)d_in[5];
    const float* wv1   = (const float*)d_in[6];
    const float* wo1   = (const float*)d_in[7];
    const float* bo1   = (const float*)d_in[8];
    const float* ln2_g = (const float*)d_in[9];
    const float* ln2_b = (const float*)d_in[10];
    const float* wq2   = (const float*)d_in[11];
    const float* wk2   = (const float*)d_in[12];
    const float* wv2   = (const float*)d_in[13];
    const float* wo2   = (const float*)d_in[14];
    const float* bo2   = (const float*)d_in[15];
    const float* ln3_g = (const float*)d_in[16];
    const float* ln3_b = (const float*)d_in[17];
    const float* wg    = (const float*)d_in[18];
    const float* bg    = (const float*)d_in[19];
    const float* wf    = (const float*)d_in[20];
    const float* bf    = (const float*)d_in[21];
    float* out = (float*)d_out;

    __half *h, *q, *kv1, *a, *act, *wt, *ench, *kv;
    float *x1, *x2;
    cudaGetSymbolAddress((void**)&h,    g_h);
    cudaGetSymbolAddress((void**)&q,    g_q);
    cudaGetSymbolAddress((void**)&kv1,  g_kv1);
    cudaGetSymbolAddress((void**)&a,    g_a);
    cudaGetSymbolAddress((void**)&act,  g_act);
    cudaGetSymbolAddress((void**)&wt,   g_wth);
    cudaGetSymbolAddress((void**)&ench, g_ench);
    cudaGetSymbolAddress((void**)&kv,   g_kv);
    cudaGetSymbolAddress((void**)&x1,   g_x1);
    cudaGetSymbolAddress((void**)&x2,   g_x2);

    cudaFuncSetAttribute(gemm_h<false, false, true, false>,
                         cudaFuncAttributeMaxDynamicSharedMemorySize, GH_SMEM);
    cudaFuncSetAttribute(gemm_h<true, true, false, false>,
                         cudaFuncAttributeMaxDynamicSharedMemorySize, GH_SMEM);
    cudaFuncSetAttribute(gemm_h<true, false, true, true>,
                         cudaFuncAttributeMaxDynamicSharedMemorySize, GH_SMEM);
    cudaFuncSetAttribute(fattn_h,
                         cudaFuncAttributeMaxDynamicSharedMemorySize, FA_SMEM);

    dim3 blk(256);
    dim3 tb32(32, 8);

    TP tp;
    tp.src[0] = wq1; tp.off[0] = OFF_WQ1; tp.K[0] = 512;  tp.N[0] = 512;
    tp.src[1] = wk1; tp.off[1] = OFF_WK1; tp.K[1] = 512;  tp.N[1] = 512;
    tp.src[2] = wv1; tp.off[2] = OFF_WV1; tp.K[2] = 512;  tp.N[2] = 512;
    tp.src[3] = wo1; tp.off[3] = OFF_WO1; tp.K[3] = 512;  tp.N[3] = 512;
    tp.src[4] = wq2; tp.off[4] = OFF_WQ2; tp.K[4] = 512;  tp.N[4] = 512;
    tp.src[5] = wo2; tp.off[5] = OFF_WO2; tp.K[5] = 512;  tp.N[5] = 512;
    tp.src[6] = wk2; tp.off[6] = OFF_WK2; tp.K[6] = 768;  tp.N[6] = 512;
    tp.src[7] = wv2; tp.off[7] = OFF_WV2; tp.K[7] = 768;  tp.N[7] = 512;
    tp.src[8] = wg;  tp.off[8] = OFF_WG;  tp.K[8] = 512;  tp.N[8] = 4096;
    tp.src[9] = wf;  tp.off[9] = OFF_WF;  tp.K[9] = 2048; tp.N[9] = 512;
    int cum = 0;
    for (int i = 0; i < 10; i++) {
        cum += (tp.N[i] >> 5) * (tp.K[i] >> 5);
        tp.cum[i] = cum;
    }
    tp.enc = enc;
    tp.encN = CROSS_ROWS * CROSS_DIM;
    int encBlocks = (tp.encN + 2047) / 2048;
    transp_all<<<cum + encBlocks, tb32>>>(tp, wt, ench);                      // 1

    dim3 g4x64(4, 64);   // N=512, M=8192
    dim3 g8x64(8, 64);   // fused KV1: N=1024, M=8192
    dim3 g8x5(8, 5);     // fused KV2: N=1024, M=616
    dim3 g32x64(32, 64); // FF1: N=4096, M=8192

    // ---- self-attention block ----
    ln_kernel<<<1024, blk>>>(x, ln1_g, ln1_b, h, ROWS);                       // 2
    gemm_h<false, false, true, false><<<g4x64, blk, GH_SMEM>>>(
        h, wt + OFF_WQ1, nullptr, nullptr, q, ROWS, DIM, DIM);                // 3
    gemm_h<false, false, true, false><<<g8x64, blk, GH_SMEM>>>(
        h, wt + OFF_WK1, nullptr, nullptr, kv1, ROWS, 1024, DIM);             // 4
    fattn_h<<<dim3(8, 8, 8), blk, FA_SMEM>>>(
        q, kv1, kv1 + 512, a, 1024, 1024, 1024);                              // 5
    gemm_h<true, true, false, false><<<g4x64, blk, GH_SMEM>>>(
        a, wt + OFF_WO1, bo1, x, x1, ROWS, DIM, DIM);                         // 6 <- profiled

    // ---- cross-attention block ----
    ln_kernel<<<1024, blk>>>(x1, ln2_g, ln2_b, h, ROWS);
    gemm_h<false, false, true, false><<<g4x64, blk, GH_SMEM>>>(
        h, wt + OFF_WQ2, nullptr, nullptr, q, ROWS, DIM, DIM);
    gemm_h<false, false, true, false><<<g8x5, blk, GH_SMEM>>>(
        ench, wt + OFF_WK2, nullptr, nullptr, kv, CROSS_ROWS, 1024, CROSS_DIM);
    fattn_h<<<dim3(8, 8, 8), blk, FA_SMEM>>>(q, kv, kv + 512, a, 77, 77, 1024);
    gemm_h<true, true, false, false><<<g4x64, blk, GH_SMEM>>>(
        a, wt + OFF_WO2, bo2, x1, x2, ROWS, DIM, DIM);

    // ---- GEGLU feed-forward (geglu fused into FF1 epilogue) ----
    ln_kernel<<<1024, blk>>>(x2, ln3_g, ln3_b, h, ROWS);
    gemm_h<true, false, true, true><<<g32x64, blk, GH_SMEM>>>(
        h, wt + OFF_WG, bg, nullptr, act, ROWS, FF2, DIM);
    gemm_h<true, true, false, false><<<g4x64, blk, GH_SMEM>>>(
        act, wt + OFF_WF, bf, x2, out, ROWS, DIM, FF_INNER);
}

// round 16
// speedup vs baseline: 1.0135x; 1.0135x over previous
#include <cuda_runtime.h>
#include <cuda_fp16.h>
#include <math.h>

// ---------------------------------------------------------------------------
// BasicTransformerBlock on GB300 — fp16 mma.sync (m16n8k16) everywhere.
// R14 champion (64-row fattn) + fused KV1/KV2 GEMMs (strided kv buffers).
// x:[8,1024,512], enc:[8,77,768]. Heads=8, dim_head=64.
// ---------------------------------------------------------------------------

#define DIM 512
#define ROWS 8192
#define CROSS_ROWS 616
#define CROSS_DIM 768
#define FF_INNER 2048
#define FF2 4096

#define OFF_WQ1 0u
#define OFF_WK1 262144u   // contiguous with WV1 for fused KV1 GEMM
#define OFF_WV1 524288u
#define OFF_WO1 786432u
#define OFF_WQ2 1048576u
#define OFF_WO2 1310720u
#define OFF_WK2 1572864u
#define OFF_WV2 1966080u  // contiguous with WK2 for fused KV2 GEMM
#define OFF_WG  2359296u
#define OFF_WF  4456448u
#define WT_TOTAL 5505024u

__device__ __half g_h[ROWS * DIM];
__device__ __half g_q[ROWS * DIM];
__device__ __half g_kv1[ROWS * 1024];
__device__ __half g_a[ROWS * DIM];
__device__ __half g_act[ROWS * FF_INNER];
__device__ __half g_kv[CROSS_ROWS * 1024];
__device__ float  g_x1[ROWS * DIM];
__device__ float  g_x2[ROWS * DIM];
__device__ __half g_wth[WT_TOTAL];
__device__ __half g_ench[CROSS_ROWS * CROSS_DIM];

// ---------------------------------------------------------------------------
// helpers
// ---------------------------------------------------------------------------
__device__ __forceinline__ void mma16(float* acc, const unsigned* a, const unsigned* b) {
    asm volatile(
        "mma.sync.aligned.m16n8k16.row.col.f32.f16.f16.f32 "
        "{%0,%1,%2,%3}, {%4,%5,%6,%7}, {%8,%9}, {%0,%1,%2,%3};"
        : "+f"(acc[0]), "+f"(acc[1]), "+f"(acc[2]), "+f"(acc[3])
        : "r"(a[0]), "r"(a[1]), "r"(a[2]), "r"(a[3]), "r"(b[0]), "r"(b[1]));
}
__device__ __forceinline__ void ldsm4(unsigned& r0, unsigned& r1, unsigned& r2, unsigned& r3,
                                      unsigned addr) {
    asm volatile("ldmatrix.sync.aligned.m8n8.x4.shared.b16 {%0,%1,%2,%3}, [%4];"
                 : "=r"(r0), "=r"(r1), "=r"(r2), "=r"(r3) : "r"(addr));
}
__device__ __forceinline__ void ldsm4t(unsigned& r0, unsigned& r1, unsigned& r2, unsigned& r3,
                                       unsigned addr) {
    asm volatile("ldmatrix.sync.aligned.m8n8.x4.trans.shared.b16 {%0,%1,%2,%3}, [%4];"
                 : "=r"(r0), "=r"(r1), "=r"(r2), "=r"(r3) : "r"(addr));
}
__device__ __forceinline__ void cpa16(unsigned dst, const void* src, bool pred) {
    int sz = pred ? 16 : 0;
    asm volatile("cp.async.cg.shared.global [%0], [%1], 16, %2;"
                 :: "r"(dst), "l"(src), "r"(sz) : "memory");
}
__device__ __forceinline__ void cpa_commit() {
    asm volatile("cp.async.commit_group;" ::: "memory");
}
template <int N>
__device__ __forceinline__ void cpa_wait() {
    asm volatile("cp.async.wait_group %0;" :: "n"(N) : "memory");
}
__device__ __forceinline__ unsigned packh2(float lo, float hi) {
    __half2 h = __floats2half2_rn(lo, hi);
    return *reinterpret_cast<unsigned*>(&h);
}
__device__ __forceinline__ float gelu_f(float x) {
    return 0.5f * x * (1.f + erff(x * 0.70710678118654752f));
}

// ---------------------------------------------------------------------------
// fused prologue: transpose+convert all 10 weights [K,N]->[N,K] half
// (weight 8 = wg gets GEGLU column interleave), plus enc f2h tail blocks.
// ---------------------------------------------------------------------------
struct TP {
    const float* src[10];
    unsigned off[10];
    int K[10], N[10], cum[10];
    const float* enc;
    int encN;
};

__global__ __launch_bounds__(256) void transp_all(TP p, __half* __restrict__ wt,
                                                  __half* __restrict__ ench)
{
    __shared__ float t[32][33];
    int bid = blockIdx.x;
    if (bid >= p.cum[9]) {
        int base = (bid - p.cum[9]) * 2048 + threadIdx.y * 32 * 8 + threadIdx.x;
#pragma unroll
        for (int i = 0; i < 8; i++) {
            int idx = base + i * 32;
            if (idx < p.encN) ench[idx] = __float2half(p.enc[idx]);
        }
        return;
    }
    int w = 0;
#pragma unroll
    for (int i = 0; i < 10; i++) if (bid >= p.cum[i]) w = i + 1;
    int tbase = w ? p.cum[w - 1] : 0;
    int tile = bid - tbase;
    int K = p.K[w], N = p.N[w];
    int tilesX = N >> 5;
    int bx = (tile % tilesX) * 32;
    int by = (tile / tilesX) * 32;
    const float* src = p.src[w];
    __half* dst = wt + p.off[w];

    int tx = threadIdx.x, ty = threadIdx.y;
#pragma unroll
    for (int i = 0; i < 4; i++)
        t[ty + 8 * i][tx] = src[(size_t)(by + ty + 8 * i) * N + bx + tx];
    __syncthreads();
#pragma unroll
    for (int i = 0; i < 4; i++) {
        int c = bx + ty + 8 * i;
        int nr = c;
        if (w == 8) {
            if (c < 2048) nr = ((c >> 4) << 5) + (c & 15);
            else { int cc = c - 2048; nr = ((cc >> 4) << 5) + 16 + (cc & 15); }
        }
        dst[(size_t)nr * K + by + tx] = __float2half(t[tx][ty + 8 * i]);
    }
}

// ---------------------------------------------------------------------------
// fp16 tensor-core GEMM: C[M,N] = A[M,K] @ BT[N,K]^T  (+bias)(+res)
// 128x128x64 tile, 256 thr, 3-stage cp.async, one barrier/tile (frozen).
// GEGLU variant fuses act = (u+bu)*gelu(g+bg) via interleaved wg.
// ---------------------------------------------------------------------------
#define HA_STG 16384
#define HB_OFF 49152
#define HB_STG 16384
#define GH_SMEM 98304

template <bool BIAS, bool RES, bool OUTH, bool GEGLU>
__global__ __launch_bounds__(256) void gemm_h(
    const __half* __restrict__ A, const __half* __restrict__ BT,
    const float* __restrict__ bias, const float* __restrict__ res,
    void* __restrict__ Cout, int M, int N, int K)
{
    extern __shared__ char smem[];
    unsigned sb = (unsigned)__cvta_generic_to_shared(smem);

    int tid = threadIdx.x;
    int lane = tid & 31, warp = tid >> 5;
    int wm = warp >> 2, wn = warp & 3;
    int m0 = blockIdx.y * 128, n0 = blockIdx.x * 128;

    int srow = tid >> 1, sch = (tid & 1) * 4;
    bool aval = (m0 + srow) < M;
    const __half* ag = A + (size_t)(aval ? m0 + srow : 0) * K + sch * 8;
    const __half* bg = BT + (size_t)(n0 + srow) * K + sch * 8;
    unsigned ssw[4];
#pragma unroll
    for (int c = 0; c < 4; c++)
        ssw[c] = srow * 128 + (((sch + c) ^ (srow & 7)) << 4);

    auto stage = [&](int t, int buf) {
        unsigned ab = sb + buf * HA_STG;
        unsigned bb = sb + HB_OFF + buf * HB_STG;
        const __half* a = ag + t * 64;
        const __half* b = bg + t * 64;
#pragma unroll
        for (int c = 0; c < 4; c++) cpa16(ab + ssw[c], a + c * 8, aval);
#pragma unroll
        for (int c = 0; c < 4; c++) cpa16(bb + ssw[c], b + c * 8, true);
        cpa_commit();
    };

    int mat = lane >> 3, lr = lane & 7;
    int rA = wm * 64 + (mat & 1) * 8 + lr;
    int rB = wn * 32 + (mat & 1) * 8 + lr;
    int cOff = mat >> 1;

    float acc[4][4][4] = {};
    int nk = K >> 6;

    stage(0, 0);
    stage(1, 1);

    for (int t = 0; t < nk; t++) {
        int buf = t % 3;
        cpa_wait<1>();
        __syncthreads();
        if (t + 2 < nk) stage(t + 2, (t + 2) % 3);
        else cpa_commit();
        unsigned abase = sb + buf * HA_STG;
        unsigned bbase = sb + HB_OFF + buf * HB_STG;
#pragma unroll
        for (int ks = 0; ks < 4; ks++) {
            int cc = ks * 2 + cOff;
            unsigned bf[4][2];
#pragma unroll
            for (int p = 0; p < 2; p++) {
                int r = rB + p * 16;
                unsigned q0, q1, q2, q3;
                ldsm4(q0, q1, q2, q3, bbase + r * 128 + ((cc ^ (r & 7)) << 4));
                bf[2 * p][0] = q0; bf[2 * p][1] = q2;
                bf[2 * p + 1][0] = q1; bf[2 * p + 1][1] = q3;
            }
#pragma unroll
            for (int i = 0; i < 4; i++) {
                int r = rA + i * 16;
                unsigned af[4];
                ldsm4(af[0], af[1], af[2], af[3],
                      abase + r * 128 + ((cc ^ (r & 7)) << 4));
#pragma unroll
                for (int j = 0; j < 4; j++)
                    mma16(acc[i][j], af, bf[j]);
            }
        }
    }

    __syncthreads();

    if (GEGLU) {
        int t32 = (n0 + wn * 32) >> 5;
        __half* actp = (__half*)Cout;
#pragma unroll
        for (int i = 0; i < 4; i++) {
            int mbase = m0 + wm * 64 + i * 16 + (lane >> 2);
#pragma unroll
            for (int j = 0; j < 2; j++) {
                int off = j * 8 + (lane & 3) * 2;
                int col = t32 * 16 + off;
                float2 bu = *(const float2*)&bias[t32 * 16 + off];
                float2 bgv = *(const float2*)&bias[2048 + t32 * 16 + off];
                int m1 = mbase, m2 = mbase + 8;
                if (m1 < M) {
                    float ux = acc[i][j][0] + bu.x, uy = acc[i][j][1] + bu.y;
                    float gx = acc[i][j + 2][0] + bgv.x, gy = acc[i][j + 2][1] + bgv.y;
                    *(__half2*)&actp[(size_t)m1 * FF_INNER + col] =
                        __floats2half2_rn(ux * gelu_f(gx), uy * gelu_f(gy));
                }
                if (m2 < M) {
                    float ux = acc[i][j][2] + bu.x, uy = acc[i][j][3] + bu.y;
                    float gx = acc[i][j + 2][2] + bgv.x, gy = acc[i][j + 2][3] + bgv.y;
                    *(__half2*)&actp[(size_t)m2 * FF_INNER + col] =
                        __floats2half2_rn(ux * gelu_f(gx), uy * gelu_f(gy));
                }
            }
        }
        return;
    }

#pragma unroll
    for (int i = 0; i < 4; i++) {
        int mbase = m0 + wm * 64 + i * 16 + (lane >> 2);
#pragma unroll
        for (int j = 0; j < 4; j++) {
            int n = n0 + wn * 32 + j * 8 + (lane & 3) * 2;
            float bx = 0.f, by = 0.f;
            if (BIAS) { float2 bb = *(const float2*)&bias[n]; bx = bb.x; by = bb.y; }
            int m1 = mbase, m2 = mbase + 8;
            if (m1 < M) {
                float vx = acc[i][j][0] + bx, vy = acc[i][j][1] + by;
                if (RES) {
                    float2 rr = *(const float2*)&res[(size_t)m1 * N + n];
                    vx += rr.x; vy += rr.y;
                }
                if (OUTH)
                    *(__half2*)&((__half*)Cout)[(size_t)m1 * N + n] = __floats2half2_rn(vx, vy);
                else
                    *(float2*)&((float*)Cout)[(size_t)m1 * N + n] = make_float2(vx, vy);
            }
            if (m2 < M) {
                float vx = acc[i][j][2] + bx, vy = acc[i][j][3] + by;
                if (RES) {
                    float2 rr = *(const float2*)&res[(size_t)m2 * N + n];
                    vx += rr.x; vy += rr.y;
                }
                if (OUTH)
                    *(__half2*)&((__half*)Cout)[(size_t)m2 * N + n] = __floats2half2_rn(vx, vy);
                else
                    *(float2*)&((float*)Cout)[(size_t)m2 * N + n] = make_float2(vx, vy);
            }
        }
    }
}

// ---------------------------------------------------------------------------
// LayerNorm: one warp per row of 512, half output
// ---------------------------------------------------------------------------
__global__ __launch_bounds__(256) void ln_kernel(
    const float* __restrict__ x, const float* __restrict__ g,
    const float* __restrict__ b, __half* __restrict__ out, int rows)
{
    int row = blockIdx.x * 8 + (threadIdx.x >> 5);
    int lane = threadIdx.x & 31;
    if (row >= rows) return;
    const float4* xr = (const float4*)(x + (size_t)row * DIM);
    float4 v[4];
    float sum = 0.f, sq = 0.f;
#pragma unroll
    for (int i = 0; i < 4; i++) {
        v[i] = xr[lane + i * 32];
        sum += v[i].x + v[i].y + v[i].z + v[i].w;
        sq  += v[i].x*v[i].x + v[i].y*v[i].y + v[i].z*v[i].z + v[i].w*v[i].w;
    }
#pragma unroll
    for (int off = 16; off; off >>= 1) {
        sum += __shfl_xor_sync(0xffffffffu, sum, off);
        sq  += __shfl_xor_sync(0xffffffffu, sq,  off);
    }
    float mean = sum * (1.f / DIM);
    float var  = sq * (1.f / DIM) - mean * mean;
    float rstd = rsqrtf(var + 1e-5f);
    __half2* outr = (__half2*)(out + (size_t)row * DIM);
#pragma unroll
    for (int i = 0; i < 4; i++) {
        int c = (lane + i * 32) * 4;
        float4 gg = *(const float4*)&g[c];
        float4 bb = *(const float4*)&b[c];
        float ox = (v[i].x - mean) * rstd * gg.x + bb.x;
        float oy = (v[i].y - mean) * rstd * gg.y + bb.y;
        float oz = (v[i].z - mean) * rstd * gg.z + bb.z;
        float ow = (v[i].w - mean) * rstd * gg.w + bb.w;
        outr[(lane + i * 32) * 2]     = __floats2half2_rn(ox, oy);
        outr[(lane + i * 32) * 2 + 1] = __floats2half2_rn(oz, ow);
    }
}

// ---------------------------------------------------------------------------
// Flash attention, fp16 mma. 128 thr (4 warps), 64 q-rows/block, 64-key tiles.
// K/V row stride = ldkv (1024 for fused kv buffers).
// ---------------------------------------------------------------------------
#define FK_STG 8192

__global__ __launch_bounds__(128) void fattn_h(
    const __half* __restrict__ Q, const __half* __restrict__ K,
    const __half* __restrict__ V, __half* __restrict__ O,
    int kRowsPerB, int Sk, int ldkv)
{
    __shared__ __half Qs[64 * 64];
    __shared__ __half Ks[2][64 * 64];
    __shared__ __half Vs[2][64 * 64];

    int tid = threadIdx.x;
    int lane = tid & 31, warp = tid >> 5;
    int b = blockIdx.z, h = blockIdx.y;
    int q0 = blockIdx.x * 64;
    size_t qbase = ((size_t)b * 1024 + q0) * DIM + h * 64;
    size_t kbase = (size_t)b * kRowsPerB * ldkv + h * 64;

    unsigned sQ = (unsigned)__cvta_generic_to_shared(Qs);
    unsigned sK = (unsigned)__cvta_generic_to_shared(Ks);
    unsigned sV = (unsigned)__cvta_generic_to_shared(Vs);

#pragma unroll
    for (int it = 0; it < 4; it++) {
        int c = tid + it * 128;
        int r = c >> 3, ch = c & 7;
        cpa16(sQ + r * 128 + ((ch ^ (r & 7)) << 4), Q + qbase + (size_t)r * DIM + ch * 8, true);
    }
    cpa_commit();

    int nkt = (Sk + 63) / 64;
#pragma unroll
    for (int t = 0; t < 2; t++) {
        if (t < nkt) {
#pragma unroll
            for (int it = 0; it < 4; it++) {
                int c = tid + it * 128;
                int r = c >> 3, ch = c & 7;
                int gr = t * 64 + r;
                bool ok = gr < Sk;
                unsigned sw = r * 128 + ((ch ^ (r & 7)) << 4);
                cpa16(sK + t * FK_STG + sw, K + kbase + (size_t)gr * ldkv + ch * 8, ok);
                cpa16(sV + t * FK_STG + sw, V + kbase + (size_t)gr * ldkv + ch * 8, ok);
            }
        }
        cpa_commit();
    }

    int mat = lane >> 3, lr = lane & 7;
    unsigned qa[4][4];
    {
        cpa_wait<2>();
        __syncthreads();
        int r = warp * 16 + (mat & 1) * 8 + lr;
#pragma unroll
        for (int ks = 0; ks < 4; ks++) {
            int cc = ks * 2 + (mat >> 1);
            ldsm4(qa[ks][0], qa[ks][1], qa[ks][2], qa[ks][3],
                  sQ + r * 128 + ((cc ^ (r & 7)) << 4));
        }
    }

    float m_[2] = {-1e30f, -1e30f};
    float l_[2] = {0.f, 0.f};
    float o[8][4] = {};

    for (int kt = 0; kt < nkt; kt++) {
        int cur = kt & 1;
        cpa_wait<1>();
        __syncthreads();

        unsigned kb = sK + cur * FK_STG;
        unsigned vb = sV + cur * FK_STG;

        float s[8][4] = {};
#pragma unroll
        for (int ks = 0; ks < 4; ks++) {
            int cc = ks * 2 + (mat >> 1);
            unsigned kf[8][2];
#pragma unroll
            for (int p = 0; p < 4; p++) {
                int r = p * 16 + (mat & 1) * 8 + lr;
                unsigned r0, r1, r2, r3;
                ldsm4(r0, r1, r2, r3, kb + r * 128 + ((cc ^ (r & 7)) << 4));
                kf[2 * p][0] = r0; kf[2 * p][1] = r2;
                kf[2 * p + 1][0] = r1; kf[2 * p + 1][1] = r3;
            }
#pragma unroll
            for (int j = 0; j < 8; j++)
                mma16(s[j], qa[ks], kf[j]);
        }
#pragma unroll
        for (int j = 0; j < 8; j++) {
            s[j][0] *= 0.125f; s[j][1] *= 0.125f; s[j][2] *= 0.125f; s[j][3] *= 0.125f;
        }
        if (kt * 64 + 64 > Sk) {
#pragma unroll
            for (int j = 0; j < 8; j++) {
                int cb = kt * 64 + j * 8 + (lane & 3) * 2;
                if (cb >= Sk)     { s[j][0] = -1e30f; s[j][2] = -1e30f; }
                if (cb + 1 >= Sk) { s[j][1] = -1e30f; s[j][3] = -1e30f; }
            }
        }
        float mx0 = -1e30f, mx1 = -1e30f;
#pragma unroll
        for (int j = 0; j < 8; j++) {
            mx0 = fmaxf(mx0, fmaxf(s[j][0], s[j][1]));
            mx1 = fmaxf(mx1, fmaxf(s[j][2], s[j][3]));
        }
#pragma unroll
        for (int off = 1; off < 4; off <<= 1) {
            mx0 = fmaxf(mx0, __shfl_xor_sync(0xffffffffu, mx0, off));
            mx1 = fmaxf(mx1, __shfl_xor_sync(0xffffffffu, mx1, off));
        }
        float mn0 = fmaxf(m_[0], mx0), mn1 = fmaxf(m_[1], mx1);
        float c0 = __expf(m_[0] - mn0), c1 = __expf(m_[1] - mn1);
        m_[0] = mn0; m_[1] = mn1;
        float sum0 = 0.f, sum1 = 0.f;
#pragma unroll
        for (int j = 0; j < 8; j++) {
            s[j][0] = __expf(s[j][0] - mn0); sum0 += s[j][0];
            s[j][1] = __expf(s[j][1] - mn0); sum0 += s[j][1];
            s[j][2] = __expf(s[j][2] - mn1); sum1 += s[j][2];
            s[j][3] = __expf(s[j][3] - mn1); sum1 += s[j][3];
        }
#pragma unroll
        for (int off = 1; off < 4; off <<= 1) {
            sum0 += __shfl_xor_sync(0xffffffffu, sum0, off);
            sum1 += __shfl_xor_sync(0xffffffffu, sum1, off);
        }
        l_[0] = l_[0] * c0 + sum0;
        l_[1] = l_[1] * c1 + sum1;
#pragma unroll
        for (int j = 0; j < 8; j++) {
            o[j][0] *= c0; o[j][1] *= c0;
            o[j][2] *= c1; o[j][3] *= c1;
        }

#pragma unroll
        for (int kk = 0; kk < 4; kk++) {
            unsigned pa[4];
            pa[0] = packh2(s[2 * kk][0],     s[2 * kk][1]);
            pa[1] = packh2(s[2 * kk][2],     s[2 * kk][3]);
            pa[2] = packh2(s[2 * kk + 1][0], s[2 * kk + 1][1]);
            pa[3] = packh2(s[2 * kk + 1][2], s[2 * kk + 1][3]);
            int r = kk * 16 + (mat & 1) * 8 + lr;
#pragma unroll
            for (int jp = 0; jp < 4; jp++) {
                int cc = jp * 2 + (mat >> 1);
                unsigned r0, r1, r2, r3;
                ldsm4t(r0, r1, r2, r3, vb + r * 128 + ((cc ^ (r & 7)) << 4));
                unsigned vf0[2] = {r0, r1};
                unsigned vf1[2] = {r2, r3};
                mma16(o[2 * jp], pa, vf0);
                mma16(o[2 * jp + 1], pa, vf1);
            }
        }
        __syncthreads();
        {
            int t = kt + 2;
            if (t < nkt) {
#pragma unroll
                for (int it = 0; it < 4; it++) {
                    int c = tid + it * 128;
                    int r = c >> 3, ch = c & 7;
                    int gr = t * 64 + r;
                    bool ok = gr < Sk;
                    unsigned sw = r * 128 + ((ch ^ (r & 7)) << 4);
                    cpa16(sK + cur * FK_STG + sw, K + kbase + (size_t)gr * ldkv + ch * 8, ok);
                    cpa16(sV + cur * FK_STG + sw, V + kbase + (size_t)gr * ldkv + ch * 8, ok);
                }
            }
            cpa_commit();
        }
    }

    float inv0 = 1.f / l_[0], inv1 = 1.f / l_[1];
    int r0 = warp * 16 + (lane >> 2);
#pragma unroll
    for (int j = 0; j < 8; j++) {
        int col = j * 8 + (lane & 3) * 2;
        *(__half2*)&O[qbase + (size_t)r0 * DIM + col] =
            __floats2half2_rn(o[j][0] * inv0, o[j][1] * inv0);
        *(__half2*)&O[qbase + (size_t)(r0 + 8) * DIM + col] =
            __floats2half2_rn(o[j][2] * inv1, o[j][3] * inv1);
    }
}

// ---------------------------------------------------------------------------
extern "C" void kernel_launch(void* const* d_in, const int* in_sizes, int n_in,
                              void* d_out, int out_size)
{
    const float* x     = (const float*)d_in[0];
    const float* enc   = (const float*)d_in[1];
    const float* ln1_g = (const float*)d_in[2];
    const float* ln1_b = (const float*)d_in[3];
    const float* wq1   = (const float*)d_in[4];
    const float* wk1   = (const float*)d_in[5];
    const float* wv1   = (const float*)d_in[6];
    const float* wo1   = (const float*)d_in[7];
    const float* bo1   = (const float*)d_in[8];
    const float* ln2_g = (const float*)d_in[9];
    const float* ln2_b = (const float*)d_in[10];
    const float* wq2   = (const float*)d_in[11];
    const float* wk2   = (const float*)d_in[12];
    const float* wv2   = (const float*)d_in[13];
    const float* wo2   = (const float*)d_in[14];
    const float* bo2   = (const float*)d_in[15];
    const float* ln3_g = (const float*)d_in[16];
    const float* ln3_b = (const float*)d_in[17];
    const float* wg    = (const float*)d_in[18];
    const float* bg    = (const float*)d_in[19];
    const float* wf    = (const float*)d_in[20];
    const float* bf    = (const float*)d_in[21];
    float* out = (float*)d_out;

    __half *h, *q, *kv1, *a, *act, *wt, *ench, *kv;
    float *x1, *x2;
    cudaGetSymbolAddress((void**)&h,    g_h);
    cudaGetSymbolAddress((void**)&q,    g_q);
    cudaGetSymbolAddress((void**)&kv1,  g_kv1);
    cudaGetSymbolAddress((void**)&a,    g_a);
    cudaGetSymbolAddress((void**)&act,  g_act);
    cudaGetSymbolAddress((void**)&wt,   g_wth);
    cudaGetSymbolAddress((void**)&ench, g_ench);
    cudaGetSymbolAddress((void**)&kv,   g_kv);
    cudaGetSymbolAddress((void**)&x1,   g_x1);
    cudaGetSymbolAddress((void**)&x2,   g_x2);

    cudaFuncSetAttribute(gemm_h<false, false, true, false>,
                         cudaFuncAttributeMaxDynamicSharedMemorySize, GH_SMEM);
    cudaFuncSetAttribute(gemm_h<true, true, false, false>,
                         cudaFuncAttributeMaxDynamicSharedMemorySize, GH_SMEM);
    cudaFuncSetAttribute(gemm_h<true, false, true, true>,
                         cudaFuncAttributeMaxDynamicSharedMemorySize, GH_SMEM);

    dim3 blk(256);
    dim3 tb32(32, 8);

    TP tp;
    tp.src[0] = wq1; tp.off[0] = OFF_WQ1; tp.K[0] = 512;  tp.N[0] = 512;
    tp.src[1] = wk1; tp.off[1] = OFF_WK1; tp.K[1] = 512;  tp.N[1] = 512;
    tp.src[2] = wv1; tp.off[2] = OFF_WV1; tp.K[2] = 512;  tp.N[2] = 512;
    tp.src[3] = wo1; tp.off[3] = OFF_WO1; tp.K[3] = 512;  tp.N[3] = 512;
    tp.src[4] = wq2; tp.off[4] = OFF_WQ2; tp.K[4] = 512;  tp.N[4] = 512;
    tp.src[5] = wo2; tp.off[5] = OFF_WO2; tp.K[5] = 512;  tp.N[5] = 512;
    tp.src[6] = wk2; tp.off[6] = OFF_WK2; tp.K[6] = 768;  tp.N[6] = 512;
    tp.src[7] = wv2; tp.off[7] = OFF_WV2; tp.K[7] = 768;  tp.N[7] = 512;
    tp.src[8] = wg;  tp.off[8] = OFF_WG;  tp.K[8] = 512;  tp.N[8] = 4096;
    tp.src[9] = wf;  tp.off[9] = OFF_WF;  tp.K[9] = 2048; tp.N[9] = 512;
    int cum = 0;
    for (int i = 0; i < 10; i++) {
        cum += (tp.N[i] >> 5) * (tp.K[i] >> 5);
        tp.cum[i] = cum;
    }
    tp.enc = enc;
    tp.encN = CROSS_ROWS * CROSS_DIM;
    int encBlocks = (tp.encN + 2047) / 2048;
    transp_all<<<cum + encBlocks, tb32>>>(tp, wt, ench);                      // 1

    dim3 g4x64(4, 64);   // N=512, M=8192
    dim3 g8x64(8, 64);   // fused KV1: N=1024, M=8192
    dim3 g8x5(8, 5);     // fused KV2: N=1024, M=616
    dim3 g32x64(32, 64); // FF1: N=4096, M=8192

    // ---- self-attention block ----
    ln_kernel<<<1024, blk>>>(x, ln1_g, ln1_b, h, ROWS);                       // 2
    gemm_h<false, false, true, false><<<g4x64, blk, GH_SMEM>>>(
        h, wt + OFF_WQ1, nullptr, nullptr, q, ROWS, DIM, DIM);                // 3
    gemm_h<false, false, true, false><<<g8x64, blk, GH_SMEM>>>(
        h, wt + OFF_WK1, nullptr, nullptr, kv1, ROWS, 1024, DIM);             // 4
    fattn_h<<<dim3(16, 8, 8), 128>>>(q, kv1, kv1 + 512, a, 1024, 1024, 1024); // 5
    gemm_h<true, true, false, false><<<g4x64, blk, GH_SMEM>>>(
        a, wt + OFF_WO1, bo1, x, x1, ROWS, DIM, DIM);                         // 6 <- profiled

    // ---- cross-attention block ----
    ln_kernel<<<1024, blk>>>(x1, ln2_g, ln2_b, h, ROWS);
    gemm_h<false, false, true, false><<<g4x64, blk, GH_SMEM>>>(
        h, wt + OFF_WQ2, nullptr, nullptr, q, ROWS, DIM, DIM);
    gemm_h<false, false, true, false><<<g8x5, blk, GH_SMEM>>>(
        ench, wt + OFF_WK2, nullptr, nullptr, kv, CROSS_ROWS, 1024, CROSS_DIM);
    fattn_h<<<dim3(16, 8, 8), 128>>>(q, kv, kv + 512, a, 77, 77, 1024);
    gemm_h<true, true, false, false><<<g4x64, blk, GH_SMEM>>>(
        a, wt + OFF_WO2, bo2, x1, x2, ROWS, DIM, DIM);

    // ---- GEGLU feed-forward (geglu fused into FF1 epilogue) ----
    ln_kernel<<<1024, blk>>>(x2, ln3_g, ln3_b, h, ROWS);
    gemm_h<true, false, true, true><<<g32x64, blk, GH_SMEM>>>(
        h, wt + OFF_WG, bg, nullptr, act, ROWS, FF2, DIM);
    gemm_h<true, true, false, false><<<g4x64, blk, GH_SMEM>>>(
        act, wt + OFF_WF, bf, x2, out, ROWS, DIM, FF_INNER);
}

// round 17
// speedup vs baseline: 1.0398x; 1.0259x over previous
#include <cuda_runtime.h>
#include <cuda_fp16.h>
#include <math.h>

// ---------------------------------------------------------------------------
// BasicTransformerBlock on GB300 — fp16 mma.sync (m16n8k16) everywhere.
// R16 champion + dual-GEMM launch merging cross-attn Q2 and KV2 (296 CTAs
// = exactly 2 waves; KV2's 40 CTAs ride Q2's partial wave).
// x:[8,1024,512], enc:[8,77,768]. Heads=8, dim_head=64.
// ---------------------------------------------------------------------------

#define DIM 512
#define ROWS 8192
#define CROSS_ROWS 616
#define CROSS_DIM 768
#define FF_INNER 2048
#define FF2 4096

#define OFF_WQ1 0u
#define OFF_WK1 262144u   // contiguous with WV1 for fused KV1 GEMM
#define OFF_WV1 524288u
#define OFF_WO1 786432u
#define OFF_WQ2 1048576u
#define OFF_WO2 1310720u
#define OFF_WK2 1572864u
#define OFF_WV2 1966080u  // contiguous with WK2 for fused KV2 GEMM
#define OFF_WG  2359296u
#define OFF_WF  4456448u
#define WT_TOTAL 5505024u

__device__ __half g_h[ROWS * DIM];
__device__ __half g_q[ROWS * DIM];
__device__ __half g_kv1[ROWS * 1024];
__device__ __half g_a[ROWS * DIM];
__device__ __half g_act[ROWS * FF_INNER];
__device__ __half g_kv[CROSS_ROWS * 1024];
__device__ float  g_x1[ROWS * DIM];
__device__ float  g_x2[ROWS * DIM];
__device__ __half g_wth[WT_TOTAL];
__device__ __half g_ench[CROSS_ROWS * CROSS_DIM];

// ---------------------------------------------------------------------------
// helpers
// ---------------------------------------------------------------------------
__device__ __forceinline__ void mma16(float* acc, const unsigned* a, const unsigned* b) {
    asm volatile(
        "mma.sync.aligned.m16n8k16.row.col.f32.f16.f16.f32 "
        "{%0,%1,%2,%3}, {%4,%5,%6,%7}, {%8,%9}, {%0,%1,%2,%3};"
        : "+f"(acc[0]), "+f"(acc[1]), "+f"(acc[2]), "+f"(acc[3])
        : "r"(a[0]), "r"(a[1]), "r"(a[2]), "r"(a[3]), "r"(b[0]), "r"(b[1]));
}
__device__ __forceinline__ void ldsm4(unsigned& r0, unsigned& r1, unsigned& r2, unsigned& r3,
                                      unsigned addr) {
    asm volatile("ldmatrix.sync.aligned.m8n8.x4.shared.b16 {%0,%1,%2,%3}, [%4];"
                 : "=r"(r0), "=r"(r1), "=r"(r2), "=r"(r3) : "r"(addr));
}
__device__ __forceinline__ void ldsm4t(unsigned& r0, unsigned& r1, unsigned& r2, unsigned& r3,
                                       unsigned addr) {
    asm volatile("ldmatrix.sync.aligned.m8n8.x4.trans.shared.b16 {%0,%1,%2,%3}, [%4];"
                 : "=r"(r0), "=r"(r1), "=r"(r2), "=r"(r3) : "r"(addr));
}
__device__ __forceinline__ void cpa16(unsigned dst, const void* src, bool pred) {
    int sz = pred ? 16 : 0;
    asm volatile("cp.async.cg.shared.global [%0], [%1], 16, %2;"
                 :: "r"(dst), "l"(src), "r"(sz) : "memory");
}
__device__ __forceinline__ void cpa_commit() {
    asm volatile("cp.async.commit_group;" ::: "memory");
}
template <int N>
__device__ __forceinline__ void cpa_wait() {
    asm volatile("cp.async.wait_group %0;" :: "n"(N) : "memory");
}
__device__ __forceinline__ unsigned packh2(float lo, float hi) {
    __half2 h = __floats2half2_rn(lo, hi);
    return *reinterpret_cast<unsigned*>(&h);
}
__device__ __forceinline__ float gelu_f(float x) {
    return 0.5f * x * (1.f + erff(x * 0.70710678118654752f));
}

// ---------------------------------------------------------------------------
// fused prologue: transpose+convert all 10 weights [K,N]->[N,K] half
// (weight 8 = wg gets GEGLU column interleave), plus enc f2h tail blocks.
// ---------------------------------------------------------------------------
struct TP {
    const float* src[10];
    unsigned off[10];
    int K[10], N[10], cum[10];
    const float* enc;
    int encN;
};

__global__ __launch_bounds__(256) void transp_all(TP p, __half* __restrict__ wt,
                                                  __half* __restrict__ ench)
{
    __shared__ float t[32][33];
    int bid = blockIdx.x;
    if (bid >= p.cum[9]) {
        int base = (bid - p.cum[9]) * 2048 + threadIdx.y * 32 * 8 + threadIdx.x;
#pragma unroll
        for (int i = 0; i < 8; i++) {
            int idx = base + i * 32;
            if (idx < p.encN) ench[idx] = __float2half(p.enc[idx]);
        }
        return;
    }
    int w = 0;
#pragma unroll
    for (int i = 0; i < 10; i++) if (bid >= p.cum[i]) w = i + 1;
    int tbase = w ? p.cum[w - 1] : 0;
    int tile = bid - tbase;
    int K = p.K[w], N = p.N[w];
    int tilesX = N >> 5;
    int bx = (tile % tilesX) * 32;
    int by = (tile / tilesX) * 32;
    const float* src = p.src[w];
    __half* dst = wt + p.off[w];

    int tx = threadIdx.x, ty = threadIdx.y;
#pragma unroll
    for (int i = 0; i < 4; i++)
        t[ty + 8 * i][tx] = src[(size_t)(by + ty + 8 * i) * N + bx + tx];
    __syncthreads();
#pragma unroll
    for (int i = 0; i < 4; i++) {
        int c = bx + ty + 8 * i;
        int nr = c;
        if (w == 8) {
            if (c < 2048) nr = ((c >> 4) << 5) + (c & 15);
            else { int cc = c - 2048; nr = ((cc >> 4) << 5) + 16 + (cc & 15); }
        }
        dst[(size_t)nr * K + by + tx] = __float2half(t[tx][ty + 8 * i]);
    }
}

// ---------------------------------------------------------------------------
// Shared GEMM core (OUTH path, no bias/res): C[M,N] = A[M,K] @ BT[N,K]^T,
// half output. 128x128x64 tile, 3-stage cp.async, one barrier per k-tile.
// Used by gemm_h<.,.,true,false> semantics and by the dual kernel.
// ---------------------------------------------------------------------------
#define HA_STG 16384
#define HB_OFF 49152
#define HB_STG 16384
#define GH_SMEM 98304

__device__ __forceinline__ void gemm_core_outh(
    const __half* __restrict__ A, const __half* __restrict__ BT,
    __half* __restrict__ C, int M, int N, int K, int m0, int n0,
    unsigned sb)
{
    int tid = threadIdx.x;
    int lane = tid & 31, warp = tid >> 5;
    int wm = warp >> 2, wn = warp & 3;

    int srow = tid >> 1, sch = (tid & 1) * 4;
    bool aval = (m0 + srow) < M;
    const __half* ag = A + (size_t)(aval ? m0 + srow : 0) * K + sch * 8;
    const __half* bg = BT + (size_t)(n0 + srow) * K + sch * 8;
    unsigned ssw[4];
#pragma unroll
    for (int c = 0; c < 4; c++)
        ssw[c] = srow * 128 + (((sch + c) ^ (srow & 7)) << 4);

    auto stage = [&](int t, int buf) {
        unsigned ab = sb + buf * HA_STG;
        unsigned bb = sb + HB_OFF + buf * HB_STG;
        const __half* a = ag + t * 64;
        const __half* b = bg + t * 64;
#pragma unroll
        for (int c = 0; c < 4; c++) cpa16(ab + ssw[c], a + c * 8, aval);
#pragma unroll
        for (int c = 0; c < 4; c++) cpa16(bb + ssw[c], b + c * 8, true);
        cpa_commit();
    };

    int mat = lane >> 3, lr = lane & 7;
    int rA = wm * 64 + (mat & 1) * 8 + lr;
    int rB = wn * 32 + (mat & 1) * 8 + lr;
    int cOff = mat >> 1;

    float acc[4][4][4] = {};
    int nk = K >> 6;

    stage(0, 0);
    stage(1, 1);

    for (int t = 0; t < nk; t++) {
        int buf = t % 3;
        cpa_wait<1>();
        __syncthreads();
        if (t + 2 < nk) stage(t + 2, (t + 2) % 3);
        else cpa_commit();
        unsigned abase = sb + buf * HA_STG;
        unsigned bbase = sb + HB_OFF + buf * HB_STG;
#pragma unroll
        for (int ks = 0; ks < 4; ks++) {
            int cc = ks * 2 + cOff;
            unsigned bf[4][2];
#pragma unroll
            for (int p = 0; p < 2; p++) {
                int r = rB + p * 16;
                unsigned q0, q1, q2, q3;
                ldsm4(q0, q1, q2, q3, bbase + r * 128 + ((cc ^ (r & 7)) << 4));
                bf[2 * p][0] = q0; bf[2 * p][1] = q2;
                bf[2 * p + 1][0] = q1; bf[2 * p + 1][1] = q3;
            }
#pragma unroll
            for (int i = 0; i < 4; i++) {
                int r = rA + i * 16;
                unsigned af[4];
                ldsm4(af[0], af[1], af[2], af[3],
                      abase + r * 128 + ((cc ^ (r & 7)) << 4));
#pragma unroll
                for (int j = 0; j < 4; j++)
                    mma16(acc[i][j], af, bf[j]);
            }
        }
    }

    __syncthreads();
#pragma unroll
    for (int i = 0; i < 4; i++) {
        int mbase = m0 + wm * 64 + i * 16 + (lane >> 2);
#pragma unroll
        for (int j = 0; j < 4; j++) {
            int n = n0 + wn * 32 + j * 8 + (lane & 3) * 2;
            int m1 = mbase, m2 = mbase + 8;
            if (m1 < M)
                *(__half2*)&C[(size_t)m1 * N + n] =
                    __floats2half2_rn(acc[i][j][0], acc[i][j][1]);
            if (m2 < M)
                *(__half2*)&C[(size_t)m2 * N + n] =
                    __floats2half2_rn(acc[i][j][2], acc[i][j][3]);
        }
    }
}

// plain OUTH GEMM kernel (wraps the core)
__global__ __launch_bounds__(256) void gemm_outh(
    const __half* __restrict__ A, const __half* __restrict__ BT,
    __half* __restrict__ C, int M, int N, int K)
{
    extern __shared__ char smem[];
    unsigned sb = (unsigned)__cvta_generic_to_shared(smem);
    gemm_core_outh(A, BT, C, M, N, K, blockIdx.y * 128, blockIdx.x * 128, sb);
}

// dual OUTH GEMM: flat grid; blocks < split do GEMM0, rest do GEMM1.
__global__ __launch_bounds__(256) void gemm_dual(
    const __half* A0, const __half* B0, __half* C0, int M0, int N0, int K0, int nt0,
    const __half* A1, const __half* B1, __half* C1, int M1, int N1, int K1, int nt1,
    int split)
{
    extern __shared__ char smem[];
    unsigned sb = (unsigned)__cvta_generic_to_shared(smem);
    int bid = blockIdx.x;
    if (bid < split) {
        gemm_core_outh(A0, B0, C0, M0, N0, K0, (bid / nt0) * 128, (bid % nt0) * 128, sb);
    } else {
        int lb = bid - split;
        gemm_core_outh(A1, B1, C1, M1, N1, K1, (lb / nt1) * 128, (lb % nt1) * 128, sb);
    }
}

// ---------------------------------------------------------------------------
// Full-featured GEMM (bias/res/float-out/GEGLU variants), frozen R9 loop.
// ---------------------------------------------------------------------------
template <bool BIAS, bool RES, bool OUTH, bool GEGLU>
__global__ __launch_bounds__(256) void gemm_h(
    const __half* __restrict__ A, const __half* __restrict__ BT,
    const float* __restrict__ bias, const float* __restrict__ res,
    void* __restrict__ Cout, int M, int N, int K)
{
    extern __shared__ char smem[];
    unsigned sb = (unsigned)__cvta_generic_to_shared(smem);

    int tid = threadIdx.x;
    int lane = tid & 31, warp = tid >> 5;
    int wm = warp >> 2, wn = warp & 3;
    int m0 = blockIdx.y * 128, n0 = blockIdx.x * 128;

    int srow = tid >> 1, sch = (tid & 1) * 4;
    bool aval = (m0 + srow) < M;
    const __half* ag = A + (size_t)(aval ? m0 + srow : 0) * K + sch * 8;
    const __half* bg = BT + (size_t)(n0 + srow) * K + sch * 8;
    unsigned ssw[4];
#pragma unroll
    for (int c = 0; c < 4; c++)
        ssw[c] = srow * 128 + (((sch + c) ^ (srow & 7)) << 4);

    auto stage = [&](int t, int buf) {
        unsigned ab = sb + buf * HA_STG;
        unsigned bb = sb + HB_OFF + buf * HB_STG;
        const __half* a = ag + t * 64;
        const __half* b = bg + t * 64;
#pragma unroll
        for (int c = 0; c < 4; c++) cpa16(ab + ssw[c], a + c * 8, aval);
#pragma unroll
        for (int c = 0; c < 4; c++) cpa16(bb + ssw[c], b + c * 8, true);
        cpa_commit();
    };

    int mat = lane >> 3, lr = lane & 7;
    int rA = wm * 64 + (mat & 1) * 8 + lr;
    int rB = wn * 32 + (mat & 1) * 8 + lr;
    int cOff = mat >> 1;

    float acc[4][4][4] = {};
    int nk = K >> 6;

    stage(0, 0);
    stage(1, 1);

    for (int t = 0; t < nk; t++) {
        int buf = t % 3;
        cpa_wait<1>();
        __syncthreads();
        if (t + 2 < nk) stage(t + 2, (t + 2) % 3);
        else cpa_commit();
        unsigned abase = sb + buf * HA_STG;
        unsigned bbase = sb + HB_OFF + buf * HB_STG;
#pragma unroll
        for (int ks = 0; ks < 4; ks++) {
            int cc = ks * 2 + cOff;
            unsigned bf[4][2];
#pragma unroll
            for (int p = 0; p < 2; p++) {
                int r = rB + p * 16;
                unsigned q0, q1, q2, q3;
                ldsm4(q0, q1, q2, q3, bbase + r * 128 + ((cc ^ (r & 7)) << 4));
                bf[2 * p][0] = q0; bf[2 * p][1] = q2;
                bf[2 * p + 1][0] = q1; bf[2 * p + 1][1] = q3;
            }
#pragma unroll
            for (int i = 0; i < 4; i++) {
                int r = rA + i * 16;
                unsigned af[4];
                ldsm4(af[0], af[1], af[2], af[3],
                      abase + r * 128 + ((cc ^ (r & 7)) << 4));
#pragma unroll
                for (int j = 0; j < 4; j++)
                    mma16(acc[i][j], af, bf[j]);
            }
        }
    }

    __syncthreads();

    if (GEGLU) {
        int t32 = (n0 + wn * 32) >> 5;
        __half* actp = (__half*)Cout;
#pragma unroll
        for (int i = 0; i < 4; i++) {
            int mbase = m0 + wm * 64 + i * 16 + (lane >> 2);
#pragma unroll
            for (int j = 0; j < 2; j++) {
                int off = j * 8 + (lane & 3) * 2;
                int col = t32 * 16 + off;
                float2 bu = *(const float2*)&bias[t32 * 16 + off];
                float2 bgv = *(const float2*)&bias[2048 + t32 * 16 + off];
                int m1 = mbase, m2 = mbase + 8;
                if (m1 < M) {
                    float ux = acc[i][j][0] + bu.x, uy = acc[i][j][1] + bu.y;
                    float gx = acc[i][j + 2][0] + bgv.x, gy = acc[i][j + 2][1] + bgv.y;
                    *(__half2*)&actp[(size_t)m1 * FF_INNER + col] =
                        __floats2half2_rn(ux * gelu_f(gx), uy * gelu_f(gy));
                }
                if (m2 < M) {
                    float ux = acc[i][j][2] + bu.x, uy = acc[i][j][3] + bu.y;
                    float gx = acc[i][j + 2][2] + bgv.x, gy = acc[i][j + 2][3] + bgv.y;
                    *(__half2*)&actp[(size_t)m2 * FF_INNER + col] =
                        __floats2half2_rn(ux * gelu_f(gx), uy * gelu_f(gy));
                }
            }
        }
        return;
    }

#pragma unroll
    for (int i = 0; i < 4; i++) {
        int mbase = m0 + wm * 64 + i * 16 + (lane >> 2);
#pragma unroll
        for (int j = 0; j < 4; j++) {
            int n = n0 + wn * 32 + j * 8 + (lane & 3) * 2;
            float bx = 0.f, by = 0.f;
            if (BIAS) { float2 bb = *(const float2*)&bias[n]; bx = bb.x; by = bb.y; }
            int m1 = mbase, m2 = mbase + 8;
            if (m1 < M) {
                float vx = acc[i][j][0] + bx, vy = acc[i][j][1] + by;
                if (RES) {
                    float2 rr = *(const float2*)&res[(size_t)m1 * N + n];
                    vx += rr.x; vy += rr.y;
                }
                if (OUTH)
                    *(__half2*)&((__half*)Cout)[(size_t)m1 * N + n] = __floats2half2_rn(vx, vy);
                else
                    *(float2*)&((float*)Cout)[(size_t)m1 * N + n] = make_float2(vx, vy);
            }
            if (m2 < M) {
                float vx = acc[i][j][2] + bx, vy = acc[i][j][3] + by;
                if (RES) {
                    float2 rr = *(const float2*)&res[(size_t)m2 * N + n];
                    vx += rr.x; vy += rr.y;
                }
                if (OUTH)
                    *(__half2*)&((__half*)Cout)[(size_t)m2 * N + n] = __floats2half2_rn(vx, vy);
                else
                    *(float2*)&((float*)Cout)[(size_t)m2 * N + n] = make_float2(vx, vy);
            }
        }
    }
}

// ---------------------------------------------------------------------------
// LayerNorm: one warp per row of 512, half output
// ---------------------------------------------------------------------------
__global__ __launch_bounds__(256) void ln_kernel(
    const float* __restrict__ x, const float* __restrict__ g,
    const float* __restrict__ b, __half* __restrict__ out, int rows)
{
    int row = blockIdx.x * 8 + (threadIdx.x >> 5);
    int lane = threadIdx.x & 31;
    if (row >= rows) return;
    const float4* xr = (const float4*)(x + (size_t)row * DIM);
    float4 v[4];
    float sum = 0.f, sq = 0.f;
#pragma unroll
    for (int i = 0; i < 4; i++) {
        v[i] = xr[lane + i * 32];
        sum += v[i].x + v[i].y + v[i].z + v[i].w;
        sq  += v[i].x*v[i].x + v[i].y*v[i].y + v[i].z*v[i].z + v[i].w*v[i].w;
    }
#pragma unroll
    for (int off = 16; off; off >>= 1) {
        sum += __shfl_xor_sync(0xffffffffu, sum, off);
        sq  += __shfl_xor_sync(0xffffffffu, sq,  off);
    }
    float mean = sum * (1.f / DIM);
    float var  = sq * (1.f / DIM) - mean * mean;
    float rstd = rsqrtf(var + 1e-5f);
    __half2* outr = (__half2*)(out + (size_t)row * DIM);
#pragma unroll
    for (int i = 0; i < 4; i++) {
        int c = (lane + i * 32) * 4;
        float4 gg = *(const float4*)&g[c];
        float4 bb = *(const float4*)&b[c];
        float ox = (v[i].x - mean) * rstd * gg.x + bb.x;
        float oy = (v[i].y - mean) * rstd * gg.y + bb.y;
        float oz = (v[i].z - mean) * rstd * gg.z + bb.z;
        float ow = (v[i].w - mean) * rstd * gg.w + bb.w;
        outr[(lane + i * 32) * 2]     = __floats2half2_rn(ox, oy);
        outr[(lane + i * 32) * 2 + 1] = __floats2half2_rn(oz, ow);
    }
}

// ---------------------------------------------------------------------------
// Flash attention, fp16 mma. 128 thr (4 warps), 64 q-rows/block, 64-key tiles.
// K/V row stride = ldkv (1024 for fused kv buffers).
// ---------------------------------------------------------------------------
#define FK_STG 8192

__global__ __launch_bounds__(128) void fattn_h(
    const __half* __restrict__ Q, const __half* __restrict__ K,
    const __half* __restrict__ V, __half* __restrict__ O,
    int kRowsPerB, int Sk, int ldkv)
{
    __shared__ __half Qs[64 * 64];
    __shared__ __half Ks[2][64 * 64];
    __shared__ __half Vs[2][64 * 64];

    int tid = threadIdx.x;
    int lane = tid & 31, warp = tid >> 5;
    int b = blockIdx.z, h = blockIdx.y;
    int q0 = blockIdx.x * 64;
    size_t qbase = ((size_t)b * 1024 + q0) * DIM + h * 64;
    size_t kbase = (size_t)b * kRowsPerB * ldkv + h * 64;

    unsigned sQ = (unsigned)__cvta_generic_to_shared(Qs);
    unsigned sK = (unsigned)__cvta_generic_to_shared(Ks);
    unsigned sV = (unsigned)__cvta_generic_to_shared(Vs);

#pragma unroll
    for (int it = 0; it < 4; it++) {
        int c = tid + it * 128;
        int r = c >> 3, ch = c & 7;
        cpa16(sQ + r * 128 + ((ch ^ (r & 7)) << 4), Q + qbase + (size_t)r * DIM + ch * 8, true);
    }
    cpa_commit();

    int nkt = (Sk + 63) / 64;
#pragma unroll
    for (int t = 0; t < 2; t++) {
        if (t < nkt) {
#pragma unroll
            for (int it = 0; it < 4; it++) {
                int c = tid + it * 128;
                int r = c >> 3, ch = c & 7;
                int gr = t * 64 + r;
                bool ok = gr < Sk;
                unsigned sw = r * 128 + ((ch ^ (r & 7)) << 4);
                cpa16(sK + t * FK_STG + sw, K + kbase + (size_t)gr * ldkv + ch * 8, ok);
                cpa16(sV + t * FK_STG + sw, V + kbase + (size_t)gr * ldkv + ch * 8, ok);
            }
        }
        cpa_commit();
    }

    int mat = lane >> 3, lr = lane & 7;
    unsigned qa[4][4];
    {
        cpa_wait<2>();
        __syncthreads();
        int r = warp * 16 + (mat & 1) * 8 + lr;
#pragma unroll
        for (int ks = 0; ks < 4; ks++) {
            int cc = ks * 2 + (mat >> 1);
            ldsm4(qa[ks][0], qa[ks][1], qa[ks][2], qa[ks][3],
                  sQ + r * 128 + ((cc ^ (r & 7)) << 4));
        }
    }

    float m_[2] = {-1e30f, -1e30f};
    float l_[2] = {0.f, 0.f};
    float o[8][4] = {};

    for (int kt = 0; kt < nkt; kt++) {
        int cur = kt & 1;
        cpa_wait<1>();
        __syncthreads();

        unsigned kb = sK + cur * FK_STG;
        unsigned vb = sV + cur * FK_STG;

        float s[8][4] = {};
#pragma unroll
        for (int ks = 0; ks < 4; ks++) {
            int cc = ks * 2 + (mat >> 1);
            unsigned kf[8][2];
#pragma unroll
            for (int p = 0; p < 4; p++) {
                int r = p * 16 + (mat & 1) * 8 + lr;
                unsigned r0, r1, r2, r3;
                ldsm4(r0, r1, r2, r3, kb + r * 128 + ((cc ^ (r & 7)) << 4));
                kf[2 * p][0] = r0; kf[2 * p][1] = r2;
                kf[2 * p + 1][0] = r1; kf[2 * p + 1][1] = r3;
            }
#pragma unroll
            for (int j = 0; j < 8; j++)
                mma16(s[j], qa[ks], kf[j]);
        }
#pragma unroll
        for (int j = 0; j < 8; j++) {
            s[j][0] *= 0.125f; s[j][1] *= 0.125f; s[j][2] *= 0.125f; s[j][3] *= 0.125f;
        }
        if (kt * 64 + 64 > Sk) {
#pragma unroll
            for (int j = 0; j < 8; j++) {
                int cb = kt * 64 + j * 8 + (lane & 3) * 2;
                if (cb >= Sk)     { s[j][0] = -1e30f; s[j][2] = -1e30f; }
                if (cb + 1 >= Sk) { s[j][1] = -1e30f; s[j][3] = -1e30f; }
            }
        }
        float mx0 = -1e30f, mx1 = -1e30f;
#pragma unroll
        for (int j = 0; j < 8; j++) {
            mx0 = fmaxf(mx0, fmaxf(s[j][0], s[j][1]));
            mx1 = fmaxf(mx1, fmaxf(s[j][2], s[j][3]));
        }
#pragma unroll
        for (int off = 1; off < 4; off <<= 1) {
            mx0 = fmaxf(mx0, __shfl_xor_sync(0xffffffffu, mx0, off));
            mx1 = fmaxf(mx1, __shfl_xor_sync(0xffffffffu, mx1, off));
        }
        float mn0 = fmaxf(m_[0], mx0), mn1 = fmaxf(m_[1], mx1);
        float c0 = __expf(m_[0] - mn0), c1 = __expf(m_[1] - mn1);
        m_[0] = mn0; m_[1] = mn1;
        float sum0 = 0.f, sum1 = 0.f;
#pragma unroll
        for (int j = 0; j < 8; j++) {
            s[j][0] = __expf(s[j][0] - mn0); sum0 += s[j][0];
            s[j][1] = __expf(s[j][1] - mn0); sum0 += s[j][1];
            s[j][2] = __expf(s[j][2] - mn1); sum1 += s[j][2];
            s[j][3] = __expf(s[j][3] - mn1); sum1 += s[j][3];
        }
#pragma unroll
        for (int off = 1; off < 4; off <<= 1) {
            sum0 += __shfl_xor_sync(0xffffffffu, sum0, off);
            sum1 += __shfl_xor_sync(0xffffffffu, sum1, off);
        }
        l_[0] = l_[0] * c0 + sum0;
        l_[1] = l_[1] * c1 + sum1;
#pragma unroll
        for (int j = 0; j < 8; j++) {
            o[j][0] *= c0; o[j][1] *= c0;
            o[j][2] *= c1; o[j][3] *= c1;
        }

#pragma unroll
        for (int kk = 0; kk < 4; kk++) {
            unsigned pa[4];
            pa[0] = packh2(s[2 * kk][0],     s[2 * kk][1]);
            pa[1] = packh2(s[2 * kk][2],     s[2 * kk][3]);
            pa[2] = packh2(s[2 * kk + 1][0], s[2 * kk + 1][1]);
            pa[3] = packh2(s[2 * kk + 1][2], s[2 * kk + 1][3]);
            int r = kk * 16 + (mat & 1) * 8 + lr;
#pragma unroll
            for (int jp = 0; jp < 4; jp++) {
                int cc = jp * 2 + (mat >> 1);
                unsigned r0, r1, r2, r3;
                ldsm4t(r0, r1, r2, r3, vb + r * 128 + ((cc ^ (r & 7)) << 4));
                unsigned vf0[2] = {r0, r1};
                unsigned vf1[2] = {r2, r3};
                mma16(o[2 * jp], pa, vf0);
                mma16(o[2 * jp + 1], pa, vf1);
            }
        }
        __syncthreads();
        {
            int t = kt + 2;
            if (t < nkt) {
#pragma unroll
                for (int it = 0; it < 4; it++) {
                    int c = tid + it * 128;
                    int r = c >> 3, ch = c & 7;
                    int gr = t * 64 + r;
                    bool ok = gr < Sk;
                    unsigned sw = r * 128 + ((ch ^ (r & 7)) << 4);
                    cpa16(sK + cur * FK_STG + sw, K + kbase + (size_t)gr * ldkv + ch * 8, ok);
                    cpa16(sV + cur * FK_STG + sw, V + kbase + (size_t)gr * ldkv + ch * 8, ok);
                }
            }
            cpa_commit();
        }
    }

    float inv0 = 1.f / l_[0], inv1 = 1.f / l_[1];
    int r0 = warp * 16 + (lane >> 2);
#pragma unroll
    for (int j = 0; j < 8; j++) {
        int col = j * 8 + (lane & 3) * 2;
        *(__half2*)&O[qbase + (size_t)r0 * DIM + col] =
            __floats2half2_rn(o[j][0] * inv0, o[j][1] * inv0);
        *(__half2*)&O[qbase + (size_t)(r0 + 8) * DIM + col] =
            __floats2half2_rn(o[j][2] * inv1, o[j][3] * inv1);
    }
}

// ---------------------------------------------------------------------------
extern "C" void kernel_launch(void* const* d_in, const int* in_sizes, int n_in,
                              void* d_out, int out_size)
{
    const float* x     = (const float*)d_in[0];
    const float* enc   = (const float*)d_in[1];
    const float* ln1_g = (const float*)d_in[2];
    const float* ln1_b = (const float*)d_in[3];
    const float* wq1   = (const float*)d_in[4];
    const float* wk1   = (const float*)d_in[5];
    const float* wv1   = (const float*)d_in[6];
    const float* wo1   = (const float*)d_in[7];
    const float* bo1   = (const float*)d_in[8];
    const float* ln2_g = (const float*)d_in[9];
    const float* ln2_b = (const float*)d_in[10];
    const float* wq2   = (const float*)d_in[11];
    const float* wk2   = (const float*)d_in[12];
    const float* wv2   = (const float*)d_in[13];
    const float* wo2   = (const float*)d_in[14];
    const float* bo2   = (const float*)d_in[15];
    const float* ln3_g = (const float*)d_in[16];
    const float* ln3_b = (const float*)d_in[17];
    const float* wg    = (const float*)d_in[18];
    const float* bg    = (const float*)d_in[19];
    const float* wf    = (const float*)d_in[20];
    const float* bf    = (const float*)d_in[21];
    float* out = (float*)d_out;

    __half *h, *q, *kv1, *a, *act, *wt, *ench, *kv;
    float *x1, *x2;
    cudaGetSymbolAddress((void**)&h,    g_h);
    cudaGetSymbolAddress((void**)&q,    g_q);
    cudaGetSymbolAddress((void**)&kv1,  g_kv1);
    cudaGetSymbolAddress((void**)&a,    g_a);
    cudaGetSymbolAddress((void**)&act,  g_act);
    cudaGetSymbolAddress((void**)&wt,   g_wth);
    cudaGetSymbolAddress((void**)&ench, g_ench);
    cudaGetSymbolAddress((void**)&kv,   g_kv);
    cudaGetSymbolAddress((void**)&x1,   g_x1);
    cudaGetSymbolAddress((void**)&x2,   g_x2);

    cudaFuncSetAttribute(gemm_outh,
                         cudaFuncAttributeMaxDynamicSharedMemorySize, GH_SMEM);
    cudaFuncSetAttribute(gemm_dual,
                         cudaFuncAttributeMaxDynamicSharedMemorySize, GH_SMEM);
    cudaFuncSetAttribute(gemm_h<true, true, false, false>,
                         cudaFuncAttributeMaxDynamicSharedMemorySize, GH_SMEM);
    cudaFuncSetAttribute(gemm_h<true, false, true, true>,
                         cudaFuncAttributeMaxDynamicSharedMemorySize, GH_SMEM);

    dim3 blk(256);
    dim3 tb32(32, 8);

    TP tp;
    tp.src[0] = wq1; tp.off[0] = OFF_WQ1; tp.K[0] = 512;  tp.N[0] = 512;
    tp.src[1] = wk1; tp.off[1] = OFF_WK1; tp.K[1] = 512;  tp.N[1] = 512;
    tp.src[2] = wv1; tp.off[2] = OFF_WV1; tp.K[2] = 512;  tp.N[2] = 512;
    tp.src[3] = wo1; tp.off[3] = OFF_WO1; tp.K[3] = 512;  tp.N[3] = 512;
    tp.src[4] = wq2; tp.off[4] = OFF_WQ2; tp.K[4] = 512;  tp.N[4] = 512;
    tp.src[5] = wo2; tp.off[5] = OFF_WO2; tp.K[5] = 512;  tp.N[5] = 512;
    tp.src[6] = wk2; tp.off[6] = OFF_WK2; tp.K[6] = 768;  tp.N[6] = 512;
    tp.src[7] = wv2; tp.off[7] = OFF_WV2; tp.K[7] = 768;  tp.N[7] = 512;
    tp.src[8] = wg;  tp.off[8] = OFF_WG;  tp.K[8] = 512;  tp.N[8] = 4096;
    tp.src[9] = wf;  tp.off[9] = OFF_WF;  tp.K[9] = 2048; tp.N[9] = 512;
    int cum = 0;
    for (int i = 0; i < 10; i++) {
        cum += (tp.N[i] >> 5) * (tp.K[i] >> 5);
        tp.cum[i] = cum;
    }
    tp.enc = enc;
    tp.encN = CROSS_ROWS * CROSS_DIM;
    int encBlocks = (tp.encN + 2047) / 2048;
    transp_all<<<cum + encBlocks, tb32>>>(tp, wt, ench);                      // 1

    dim3 g4x64(4, 64);   // N=512, M=8192
    dim3 g8x64(8, 64);   // fused KV1: N=1024, M=8192
    dim3 g32x64(32, 64); // FF1: N=4096, M=8192

    // ---- self-attention block ----
    ln_kernel<<<1024, blk>>>(x, ln1_g, ln1_b, h, ROWS);                       // 2
    gemm_outh<<<g4x64, blk, GH_SMEM>>>(h, wt + OFF_WQ1, q, ROWS, DIM, DIM);   // 3
    gemm_outh<<<g8x64, blk, GH_SMEM>>>(h, wt + OFF_WK1, kv1, ROWS, 1024, DIM);// 4
    fattn_h<<<dim3(16, 8, 8), 128>>>(q, kv1, kv1 + 512, a, 1024, 1024, 1024); // 5
    gemm_h<true, true, false, false><<<g4x64, blk, GH_SMEM>>>(
        a, wt + OFF_WO1, bo1, x, x1, ROWS, DIM, DIM);                         // 6 <- profiled

    // ---- cross-attention block ----
    ln_kernel<<<1024, blk>>>(x1, ln2_g, ln2_b, h, ROWS);
    // dual launch: Q2 (256 CTAs, m-major flat) + KV2 (40 CTAs) = 296 CTAs
    gemm_dual<<<296, blk, GH_SMEM>>>(
        h, wt + OFF_WQ2, q, ROWS, 512, 512, 4,
        ench, wt + OFF_WK2, kv, CROSS_ROWS, 1024, CROSS_DIM, 8,
        256);
    fattn_h<<<dim3(16, 8, 8), 128>>>(q, kv, kv + 512, a, 77, 77, 1024);
    gemm_h<true, true, false, false><<<g4x64, blk, GH_SMEM>>>(
        a, wt + OFF_WO2, bo2, x1, x2, ROWS, DIM, DIM);

    // ---- GEGLU feed-forward (geglu fused into FF1 epilogue) ----
    ln_kernel<<<1024, blk>>>(x2, ln3_g, ln3_b, h, ROWS);
    gemm_h<true, false, true, true><<<g32x64, blk, GH_SMEM>>>(
        h, wt + OFF_WG, bg, nullptr, act, ROWS, FF2, DIM);
    gemm_h<true, true, false, false><<<g4x64, blk, GH_SMEM>>>(
        act, wt + OFF_WF, bf, x2, out, ROWS, DIM, FF_INNER);
}